// round 1
// baseline (speedup 1.0000x reference)
#include <cuda_runtime.h>
#include <math.h>
#include <stdint.h>

// Problem constants
#define BSZ    4096
#define NST    4
#define EMBED  2048
#define DFF    8192
#define IN_DIM 8192   // N*BLOCK = 4*2048
#define BLK    2048

// Scratch (device globals; no allocations allowed)
__device__ float g_branch[BSZ * EMBED];      // 32 MB
__device__ float g_H[(size_t)BSZ * DFF];     // 128 MB
__device__ float g_wout[BSZ * NST];          // write_out gates

__device__ __forceinline__ float sigf(float v) { return 1.0f / (1.0f + expf(-v)); }
__device__ __forceinline__ float softplusf(float v) {
    return (v > 15.0f) ? v : log1pf(expf(v));
}
__device__ __forceinline__ float geluf(float v) {
    // jax.nn.gelu approximate=True (tanh form)
    const float c = 0.7978845608028654f;
    float t = tanhf(c * (v + 0.044715f * v * v * v));
    return 0.5f * v * (1.0f + t);
}

// ---------------------------------------------------------------------------
// Kernel A: per-row RMSNorm stats + 30 projections + scalar math + Phi@x + branch
// grid = 4096 blocks (one row), 256 threads
// ---------------------------------------------------------------------------
__global__ void __launch_bounds__(256) kernelA(
    const float* __restrict__ x,
    const float* __restrict__ p_ri,   const float* __restrict__ p_wo,
    const float* __restrict__ a_ri,   const float* __restrict__ a_wo,
    const float* __restrict__ W_ri,   const float* __restrict__ W_wo,
    const float* __restrict__ ldt_c,  const float* __restrict__ ldt_d,
    const float* __restrict__ W_dtc,  const float* __restrict__ b_dtc,
    const float* __restrict__ W_dtd,  const float* __restrict__ b_dtd,
    const float* __restrict__ cA,     const float* __restrict__ W_conv,
    const float* __restrict__ ddiag,  const float* __restrict__ W_diss,
    float* __restrict__ out)
{
    __shared__ float sx[IN_DIM];          // 32 KB: full row of x
    __shared__ float spart[31 * 8];       // per-warp partials
    __shared__ float sdots[31];
    __shared__ float sPhi[16];
    __shared__ float srin[4];

    const int row = blockIdx.x;
    const int tid = threadIdx.x;

    // Load x row (8192 floats) into smem via float4
    {
        const float4* xr = (const float4*)(x + (size_t)row * IN_DIM);
        float4* sx4 = (float4*)sx;
        #pragma unroll
        for (int i = tid; i < IN_DIM / 4; i += 256) sx4[i] = xr[i];
    }
    __syncthreads();

    // 31 simultaneous dot products: 0-3 W_ri, 4-7 W_wo, 8-23 W_conv,
    // 24-27 W_diss, 28 W_dtc, 29 W_dtd, 30 = sum(x^2)
    float acc[31];
    #pragma unroll
    for (int j = 0; j < 31; j++) acc[j] = 0.0f;

    for (int k = tid; k < IN_DIM; k += 256) {
        float xv = sx[k];
        acc[30] = fmaf(xv, xv, acc[30]);
        #pragma unroll
        for (int j = 0; j < 4; j++)  acc[j]      = fmaf(xv, W_ri[j * IN_DIM + k],   acc[j]);
        #pragma unroll
        for (int j = 0; j < 4; j++)  acc[4 + j]  = fmaf(xv, W_wo[j * IN_DIM + k],   acc[4 + j]);
        #pragma unroll
        for (int j = 0; j < 16; j++) acc[8 + j]  = fmaf(xv, W_conv[j * IN_DIM + k], acc[8 + j]);
        #pragma unroll
        for (int j = 0; j < 4; j++)  acc[24 + j] = fmaf(xv, W_diss[j * IN_DIM + k], acc[24 + j]);
        acc[28] = fmaf(xv, W_dtc[k], acc[28]);
        acc[29] = fmaf(xv, W_dtd[k], acc[29]);
    }

    // Reduce: warp shuffle then cross-warp in smem
    const int lane = tid & 31, wid = tid >> 5;
    #pragma unroll
    for (int j = 0; j < 31; j++) {
        float v = acc[j];
        #pragma unroll
        for (int o = 16; o > 0; o >>= 1) v += __shfl_down_sync(0xffffffffu, v, o);
        if (lane == 0) spart[j * 8 + wid] = v;
    }
    __syncthreads();
    if (tid < 31) {
        float s = 0.0f;
        #pragma unroll
        for (int w = 0; w < 8; w++) s += spart[tid * 8 + w];
        sdots[tid] = s;
    }
    __syncthreads();

    // Scalar math on thread 0
    if (tid == 0) {
        const float rstd = rsqrtf(sdots[30] * (1.0f / (float)IN_DIM) + 1.1920929e-7f);
        float h[30];
        #pragma unroll
        for (int j = 0; j < 30; j++) h[j] = sdots[j] * rstd;

        const float ari = a_ri[0], awo = a_wo[0];
        float wo_local[4];
        #pragma unroll
        for (int n = 0; n < 4; n++) {
            srin[n]     = sigf(ari * h[n] + p_ri[n]);
            wo_local[n] = 2.0f * sigf(awo * h[4 + n] + p_wo[n]);
            g_wout[row * 4 + n] = wo_local[n];
        }

        const float dtc = 1e-3f + 0.999f * sigf(ldt_c[0] + h[28] + b_dtc[0]);
        const float dtd = 1e-3f + 0.999f * sigf(ldt_d[0] + h[29] + b_dtd[0]);

        float Mm[4][4];
        #pragma unroll
        for (int i = 0; i < 4; i++)
            #pragma unroll
            for (int j = 0; j < 4; j++)
                Mm[i][j] = cA[i * 4 + j] + h[8 + i * 4 + j];

        float S[4][4];
        #pragma unroll
        for (int i = 0; i < 4; i++)
            #pragma unroll
            for (int j = 0; j < 4; j++)
                S[i][j] = 0.5f * (Mm[i][j] - Mm[j][i]) * dtc;

        float ehD[4];
        #pragma unroll
        for (int n = 0; n < 4; n++) {
            float dd = softplusf(ddiag[n] + h[24 + n]);
            ehD[n] = expf(-0.5f * dtd * dd);
        }

        // Cayley: solve (I - S) X = (I + S), Gauss-Jordan (I-S well conditioned)
        float A[4][4], X[4][4];
        #pragma unroll
        for (int i = 0; i < 4; i++)
            #pragma unroll
            for (int j = 0; j < 4; j++) {
                float id = (i == j) ? 1.0f : 0.0f;
                A[i][j] = id - S[i][j];
                X[i][j] = id + S[i][j];
            }
        #pragma unroll
        for (int p = 0; p < 4; p++) {
            float inv = 1.0f / A[p][p];
            #pragma unroll
            for (int j = 0; j < 4; j++) { A[p][j] *= inv; X[p][j] *= inv; }
            #pragma unroll
            for (int r = 0; r < 4; r++) {
                if (r == p) continue;
                float f = A[r][p];
                #pragma unroll
                for (int j = 0; j < 4; j++) {
                    A[r][j] = fmaf(-f, A[p][j], A[r][j]);
                    X[r][j] = fmaf(-f, X[p][j], X[r][j]);
                }
            }
        }
        #pragma unroll
        for (int i = 0; i < 4; i++)
            #pragma unroll
            for (int j = 0; j < 4; j++)
                sPhi[i * 4 + j] = ehD[i] * X[i][j] * ehD[j];
    }
    __syncthreads();

    // Phase 3: branch = sum_n rin[n]*x[n,:], out = Phi @ x
    const float r0 = srin[0], r1 = srin[1], r2 = srin[2], r3 = srin[3];
    float ph[16];
    #pragma unroll
    for (int i = 0; i < 16; i++) ph[i] = sPhi[i];

    for (int c = tid; c < BLK; c += 256) {
        float x0 = sx[c], x1 = sx[BLK + c], x2 = sx[2 * BLK + c], x3 = sx[3 * BLK + c];
        g_branch[(size_t)row * BLK + c] = r0 * x0 + r1 * x1 + r2 * x2 + r3 * x3;
        #pragma unroll
        for (int i = 0; i < 4; i++) {
            out[(size_t)row * IN_DIM + i * BLK + c] =
                ph[i * 4 + 0] * x0 + ph[i * 4 + 1] * x1 + ph[i * 4 + 2] * x2 + ph[i * 4 + 3] * x3;
        }
    }
}

// ---------------------------------------------------------------------------
// GEMM1: g_H = gelu(g_branch @ W1)   [4096,2048] x [2048,8192] -> [4096,8192]
// Classic fp32 tiled SGEMM: 128x128 block tile, BK=16, 8x8 per thread, 256 thr
// ---------------------------------------------------------------------------
__global__ void __launch_bounds__(256) gemm1_gelu(const float* __restrict__ W1)
{
    constexpr int Kdim = EMBED;  // 2048
    constexpr int Ndim = DFF;    // 8192
    __shared__ float As[16][128];
    __shared__ float Bs[16][128];

    const int tid  = threadIdx.x;
    const int tx   = tid % 16, ty = tid / 16;
    const int bRow = blockIdx.y * 128;
    const int bCol = blockIdx.x * 128;

    const int aRow = tid >> 2;          // 0..63
    const int aCol = (tid & 3) * 4;     // 0,4,8,12
    const int bRowL = tid >> 5;         // 0..7
    const int bColL = (tid & 31) * 4;   // 0..124

    float accv[8][8] = {};

    for (int k0 = 0; k0 < Kdim; k0 += 16) {
        #pragma unroll
        for (int r = 0; r < 2; r++) {
            float4 v = *(const float4*)(g_branch + (size_t)(bRow + aRow + r * 64) * Kdim + k0 + aCol);
            As[aCol + 0][aRow + r * 64] = v.x;
            As[aCol + 1][aRow + r * 64] = v.y;
            As[aCol + 2][aRow + r * 64] = v.z;
            As[aCol + 3][aRow + r * 64] = v.w;
        }
        #pragma unroll
        for (int r = 0; r < 2; r++) {
            float4 v = *(const float4*)(W1 + (size_t)(k0 + bRowL + r * 8) * Ndim + bCol + bColL);
            *(float4*)&Bs[bRowL + r * 8][bColL] = v;
        }
        __syncthreads();
        #pragma unroll
        for (int kk = 0; kk < 16; kk++) {
            float ra[8], rb[8];
            #pragma unroll
            for (int i = 0; i < 8; i++) ra[i] = As[kk][ty * 8 + i];
            #pragma unroll
            for (int j = 0; j < 8; j++) rb[j] = Bs[kk][tx * 8 + j];
            #pragma unroll
            for (int i = 0; i < 8; i++)
                #pragma unroll
                for (int j = 0; j < 8; j++)
                    accv[i][j] = fmaf(ra[i], rb[j], accv[i][j]);
        }
        __syncthreads();
    }

    #pragma unroll
    for (int i = 0; i < 8; i++) {
        const int r = bRow + ty * 8 + i;
        #pragma unroll
        for (int j = 0; j < 8; j += 4) {
            float4 v;
            v.x = geluf(accv[i][j + 0]);
            v.y = geluf(accv[i][j + 1]);
            v.z = geluf(accv[i][j + 2]);
            v.w = geluf(accv[i][j + 3]);
            *(float4*)(g_H + (size_t)r * Ndim + bCol + tx * 8 + j) = v;
        }
    }
}

// ---------------------------------------------------------------------------
// GEMM2: y = g_H @ W2; fused epilogue: out[b,n,:] += wout[b,n] * y[b,:]
// [4096,8192] x [8192,2048] -> [4096,2048]
// ---------------------------------------------------------------------------
__global__ void __launch_bounds__(256) gemm2_fused(const float* __restrict__ W2,
                                                   float* __restrict__ out)
{
    constexpr int Kdim = DFF;    // 8192
    constexpr int Ndim = EMBED;  // 2048
    __shared__ float As[16][128];
    __shared__ float Bs[16][128];

    const int tid  = threadIdx.x;
    const int tx   = tid % 16, ty = tid / 16;
    const int bRow = blockIdx.y * 128;
    const int bCol = blockIdx.x * 128;

    const int aRow = tid >> 2;
    const int aCol = (tid & 3) * 4;
    const int bRowL = tid >> 5;
    const int bColL = (tid & 31) * 4;

    float accv[8][8] = {};

    for (int k0 = 0; k0 < Kdim; k0 += 16) {
        #pragma unroll
        for (int r = 0; r < 2; r++) {
            float4 v = *(const float4*)(g_H + (size_t)(bRow + aRow + r * 64) * Kdim + k0 + aCol);
            As[aCol + 0][aRow + r * 64] = v.x;
            As[aCol + 1][aRow + r * 64] = v.y;
            As[aCol + 2][aRow + r * 64] = v.z;
            As[aCol + 3][aRow + r * 64] = v.w;
        }
        #pragma unroll
        for (int r = 0; r < 2; r++) {
            float4 v = *(const float4*)(W2 + (size_t)(k0 + bRowL + r * 8) * Ndim + bCol + bColL);
            *(float4*)&Bs[bRowL + r * 8][bColL] = v;
        }
        __syncthreads();
        #pragma unroll
        for (int kk = 0; kk < 16; kk++) {
            float ra[8], rb[8];
            #pragma unroll
            for (int i = 0; i < 8; i++) ra[i] = As[kk][ty * 8 + i];
            #pragma unroll
            for (int j = 0; j < 8; j++) rb[j] = Bs[kk][tx * 8 + j];
            #pragma unroll
            for (int i = 0; i < 8; i++)
                #pragma unroll
                for (int j = 0; j < 8; j++)
                    accv[i][j] = fmaf(ra[i], rb[j], accv[i][j]);
        }
        __syncthreads();
    }

    // Fused: out[r, n*2048 + c] += wout[r*4+n] * y[r, c]
    #pragma unroll
    for (int i = 0; i < 8; i++) {
        const int r = bRow + ty * 8 + i;
        float w[4];
        #pragma unroll
        for (int n = 0; n < 4; n++) w[n] = g_wout[r * 4 + n];
        const int c = bCol + tx * 8;
        #pragma unroll
        for (int jj = 0; jj < 2; jj++) {
            float4 yv;
            yv.x = accv[i][jj * 4 + 0];
            yv.y = accv[i][jj * 4 + 1];
            yv.z = accv[i][jj * 4 + 2];
            yv.w = accv[i][jj * 4 + 3];
            #pragma unroll
            for (int n = 0; n < 4; n++) {
                float4* op = (float4*)(out + (size_t)r * IN_DIM + n * BLK + c + jj * 4);
                float4 o = *op;
                o.x = fmaf(w[n], yv.x, o.x);
                o.y = fmaf(w[n], yv.y, o.y);
                o.z = fmaf(w[n], yv.z, o.z);
                o.w = fmaf(w[n], yv.w, o.w);
                *op = o;
            }
        }
    }
}

// ---------------------------------------------------------------------------
extern "C" void kernel_launch(void* const* d_in, const int* in_sizes, int n_in,
                              void* d_out, int out_size)
{
    const float* x      = (const float*)d_in[0];
    const float* p_ri   = (const float*)d_in[1];
    const float* p_wo   = (const float*)d_in[2];
    const float* a_ri   = (const float*)d_in[3];
    const float* a_wo   = (const float*)d_in[4];
    const float* W_ri   = (const float*)d_in[5];
    const float* W_wo   = (const float*)d_in[6];
    const float* ldt_c  = (const float*)d_in[7];
    const float* ldt_d  = (const float*)d_in[8];
    const float* W_dtc  = (const float*)d_in[9];
    const float* b_dtc  = (const float*)d_in[10];
    const float* W_dtd  = (const float*)d_in[11];
    const float* b_dtd  = (const float*)d_in[12];
    const float* cA     = (const float*)d_in[13];
    const float* W_conv = (const float*)d_in[14];
    const float* ddiag  = (const float*)d_in[15];
    const float* W_diss = (const float*)d_in[16];
    const float* W1     = (const float*)d_in[17];
    const float* W2     = (const float*)d_in[18];
    float* out = (float*)d_out;

    kernelA<<<BSZ, 256>>>(x, p_ri, p_wo, a_ri, a_wo, W_ri, W_wo,
                          ldt_c, ldt_d, W_dtc, b_dtc, W_dtd, b_dtd,
                          cA, W_conv, ddiag, W_diss, out);

    dim3 g1(DFF / 128, BSZ / 128);    // (64, 32)
    gemm1_gelu<<<g1, 256>>>(W1);

    dim3 g2(EMBED / 128, BSZ / 128);  // (16, 32)
    gemm2_fused<<<g2, 256>>>(W2, out);
}

// round 2
// speedup vs baseline: 2.6084x; 2.6084x over previous
#include <cuda_runtime.h>
#include <math.h>
#include <stdint.h>

// Problem constants
#define BSZ    4096
#define NST    4
#define EMBED  2048
#define DFF    8192
#define IN_DIM 8192   // N*BLOCK = 4*2048
#define BLK    2048

// Scratch (device globals; no allocations allowed)
__device__ float g_branch[BSZ * EMBED];      // 32 MB
__device__ float g_H[(size_t)BSZ * DFF];     // 128 MB
__device__ float g_wout[BSZ * NST];          // write_out gates

__device__ __forceinline__ float sigf(float v) { return 1.0f / (1.0f + expf(-v)); }
__device__ __forceinline__ float softplusf(float v) {
    return (v > 15.0f) ? v : log1pf(expf(v));
}
__device__ __forceinline__ float geluf(float v) {
    // jax.nn.gelu approximate=True (tanh form)
    const float c = 0.7978845608028654f;
    float t = tanhf(c * (v + 0.044715f * v * v * v));
    return 0.5f * v * (1.0f + t);
}
__device__ __forceinline__ float to_tf32(float x) {
    uint32_t u;
    asm("cvt.rna.tf32.f32 %0, %1;" : "=r"(u) : "f"(x));
    return __uint_as_float(u);
}
__device__ __forceinline__ void mma_tf32(float* c, const uint32_t* a, const uint32_t* b) {
    asm volatile("mma.sync.aligned.m16n8k8.row.col.f32.tf32.tf32.f32 "
                 "{%0,%1,%2,%3}, {%4,%5,%6,%7}, {%8,%9}, {%0,%1,%2,%3};"
                 : "+f"(c[0]), "+f"(c[1]), "+f"(c[2]), "+f"(c[3])
                 : "r"(a[0]), "r"(a[1]), "r"(a[2]), "r"(a[3]),
                   "r"(b[0]), "r"(b[1]));
}

// ---------------------------------------------------------------------------
// Kernel A: per-row RMSNorm stats + 30 projections + scalar math + Phi@x + branch
// ---------------------------------------------------------------------------
__global__ void __launch_bounds__(256) kernelA(
    const float* __restrict__ x,
    const float* __restrict__ p_ri,   const float* __restrict__ p_wo,
    const float* __restrict__ a_ri,   const float* __restrict__ a_wo,
    const float* __restrict__ W_ri,   const float* __restrict__ W_wo,
    const float* __restrict__ ldt_c,  const float* __restrict__ ldt_d,
    const float* __restrict__ W_dtc,  const float* __restrict__ b_dtc,
    const float* __restrict__ W_dtd,  const float* __restrict__ b_dtd,
    const float* __restrict__ cA,     const float* __restrict__ W_conv,
    const float* __restrict__ ddiag,  const float* __restrict__ W_diss,
    float* __restrict__ out)
{
    __shared__ float sx[IN_DIM];
    __shared__ float spart[31 * 8];
    __shared__ float sdots[31];
    __shared__ float sPhi[16];
    __shared__ float srin[4];

    const int row = blockIdx.x;
    const int tid = threadIdx.x;

    {
        const float4* xr = (const float4*)(x + (size_t)row * IN_DIM);
        float4* sx4 = (float4*)sx;
        #pragma unroll
        for (int i = tid; i < IN_DIM / 4; i += 256) sx4[i] = xr[i];
    }
    __syncthreads();

    float acc[31];
    #pragma unroll
    for (int j = 0; j < 31; j++) acc[j] = 0.0f;

    for (int k = tid; k < IN_DIM; k += 256) {
        float xv = sx[k];
        acc[30] = fmaf(xv, xv, acc[30]);
        #pragma unroll
        for (int j = 0; j < 4; j++)  acc[j]      = fmaf(xv, W_ri[j * IN_DIM + k],   acc[j]);
        #pragma unroll
        for (int j = 0; j < 4; j++)  acc[4 + j]  = fmaf(xv, W_wo[j * IN_DIM + k],   acc[4 + j]);
        #pragma unroll
        for (int j = 0; j < 16; j++) acc[8 + j]  = fmaf(xv, W_conv[j * IN_DIM + k], acc[8 + j]);
        #pragma unroll
        for (int j = 0; j < 4; j++)  acc[24 + j] = fmaf(xv, W_diss[j * IN_DIM + k], acc[24 + j]);
        acc[28] = fmaf(xv, W_dtc[k], acc[28]);
        acc[29] = fmaf(xv, W_dtd[k], acc[29]);
    }

    const int lane = tid & 31, wid = tid >> 5;
    #pragma unroll
    for (int j = 0; j < 31; j++) {
        float v = acc[j];
        #pragma unroll
        for (int o = 16; o > 0; o >>= 1) v += __shfl_down_sync(0xffffffffu, v, o);
        if (lane == 0) spart[j * 8 + wid] = v;
    }
    __syncthreads();
    if (tid < 31) {
        float s = 0.0f;
        #pragma unroll
        for (int w = 0; w < 8; w++) s += spart[tid * 8 + w];
        sdots[tid] = s;
    }
    __syncthreads();

    if (tid == 0) {
        const float rstd = rsqrtf(sdots[30] * (1.0f / (float)IN_DIM) + 1.1920929e-7f);
        float h[30];
        #pragma unroll
        for (int j = 0; j < 30; j++) h[j] = sdots[j] * rstd;

        const float ari = a_ri[0], awo = a_wo[0];
        #pragma unroll
        for (int n = 0; n < 4; n++) {
            srin[n] = sigf(ari * h[n] + p_ri[n]);
            g_wout[row * 4 + n] = 2.0f * sigf(awo * h[4 + n] + p_wo[n]);
        }

        const float dtc = 1e-3f + 0.999f * sigf(ldt_c[0] + h[28] + b_dtc[0]);
        const float dtd = 1e-3f + 0.999f * sigf(ldt_d[0] + h[29] + b_dtd[0]);

        float Mm[4][4];
        #pragma unroll
        for (int i = 0; i < 4; i++)
            #pragma unroll
            for (int j = 0; j < 4; j++)
                Mm[i][j] = cA[i * 4 + j] + h[8 + i * 4 + j];

        float S[4][4];
        #pragma unroll
        for (int i = 0; i < 4; i++)
            #pragma unroll
            for (int j = 0; j < 4; j++)
                S[i][j] = 0.5f * (Mm[i][j] - Mm[j][i]) * dtc;

        float ehD[4];
        #pragma unroll
        for (int n = 0; n < 4; n++) {
            float dd = softplusf(ddiag[n] + h[24 + n]);
            ehD[n] = expf(-0.5f * dtd * dd);
        }

        float A[4][4], X[4][4];
        #pragma unroll
        for (int i = 0; i < 4; i++)
            #pragma unroll
            for (int j = 0; j < 4; j++) {
                float id = (i == j) ? 1.0f : 0.0f;
                A[i][j] = id - S[i][j];
                X[i][j] = id + S[i][j];
            }
        #pragma unroll
        for (int p = 0; p < 4; p++) {
            float inv = 1.0f / A[p][p];
            #pragma unroll
            for (int j = 0; j < 4; j++) { A[p][j] *= inv; X[p][j] *= inv; }
            #pragma unroll
            for (int r = 0; r < 4; r++) {
                if (r == p) continue;
                float f = A[r][p];
                #pragma unroll
                for (int j = 0; j < 4; j++) {
                    A[r][j] = fmaf(-f, A[p][j], A[r][j]);
                    X[r][j] = fmaf(-f, X[p][j], X[r][j]);
                }
            }
        }
        #pragma unroll
        for (int i = 0; i < 4; i++)
            #pragma unroll
            for (int j = 0; j < 4; j++)
                sPhi[i * 4 + j] = ehD[i] * X[i][j] * ehD[j];
    }
    __syncthreads();

    const float r0 = srin[0], r1 = srin[1], r2 = srin[2], r3 = srin[3];
    float ph[16];
    #pragma unroll
    for (int i = 0; i < 16; i++) ph[i] = sPhi[i];

    for (int c = tid; c < BLK; c += 256) {
        float x0 = sx[c], x1 = sx[BLK + c], x2 = sx[2 * BLK + c], x3 = sx[3 * BLK + c];
        g_branch[(size_t)row * BLK + c] = r0 * x0 + r1 * x1 + r2 * x2 + r3 * x3;
        #pragma unroll
        for (int i = 0; i < 4; i++) {
            out[(size_t)row * IN_DIM + i * BLK + c] =
                ph[i * 4 + 0] * x0 + ph[i * 4 + 1] * x1 + ph[i * 4 + 2] * x2 + ph[i * 4 + 3] * x3;
        }
    }
}

// ---------------------------------------------------------------------------
// TF32 tensor-core GEMM, 128x128 CTA tile, BK=16, 8 warps (2x4), warp 64x32.
// PHASE 1: g_H = gelu(g_branch @ W1)          (Kdim=2048, Ndim=8192)
// PHASE 2: out[b,n,:] += wout[b,n]*(g_H@W2)   (Kdim=8192, Ndim=2048)
// Double-buffered smem, tf32 conversion (rna) on fill.
// ---------------------------------------------------------------------------
#define BM 128
#define BN 128
#define BKT 16
#define SAS (BM + 8)   // 136: row stride; 136 % 32 == 8 -> conflict-free frags
#define SBS (BN + 8)

template<int Kdim, int Ndim, int PHASE>
__global__ void __launch_bounds__(256, 2) mma_gemm(
    const float* __restrict__ Bg,     // weights (W1 or W2)
    float* __restrict__ Cout)         // g_H (phase1) or out (phase2)
{
    __shared__ float As[2][BKT][SAS];
    __shared__ float Bs[2][BKT][SBS];

    const float* __restrict__ Ag = (PHASE == 1) ? g_branch : g_H;

    const int tid  = threadIdx.x;
    const int wid  = tid >> 5;
    const int lane = tid & 31;
    const int g = lane >> 2, t = lane & 3;
    const int wm = (wid >> 2) * 64;     // 0 / 64
    const int wn = (wid & 3) * 32;      // 0,32,64,96
    const int bm = blockIdx.y * BM;
    const int bn = blockIdx.x * BN;

    // fill indices
    const int am = tid >> 2;            // 0..63  (A row within tile)
    const int ak = (tid & 3) * 4;       // 0,4,8,12 (A k within tile)
    const int bk = tid >> 4;            // 0..15 (B k)
    const int bn0 = (tid & 15) * 4;     // B n: two chunks at bn0, bn0+64

    float4 aR[2], bR[2];

    float acc[4][4][4];
    #pragma unroll
    for (int i = 0; i < 4; i++)
        #pragma unroll
        for (int j = 0; j < 4; j++)
            #pragma unroll
            for (int q = 0; q < 4; q++) acc[i][j][q] = 0.0f;

    // ---- prologue: tile 0 ----
    #pragma unroll
    for (int r = 0; r < 2; r++)
        aR[r] = *(const float4*)(Ag + (size_t)(bm + am + r * 64) * Kdim + ak);
    #pragma unroll
    for (int r = 0; r < 2; r++)
        bR[r] = *(const float4*)(Bg + (size_t)bk * Ndim + bn + bn0 + r * 64);
    #pragma unroll
    for (int r = 0; r < 2; r++) {
        As[0][ak + 0][am + r * 64] = to_tf32(aR[r].x);
        As[0][ak + 1][am + r * 64] = to_tf32(aR[r].y);
        As[0][ak + 2][am + r * 64] = to_tf32(aR[r].z);
        As[0][ak + 3][am + r * 64] = to_tf32(aR[r].w);
    }
    #pragma unroll
    for (int r = 0; r < 2; r++) {
        float4 v;
        v.x = to_tf32(bR[r].x); v.y = to_tf32(bR[r].y);
        v.z = to_tf32(bR[r].z); v.w = to_tf32(bR[r].w);
        *(float4*)&Bs[0][bk][bn0 + r * 64] = v;
    }
    __syncthreads();

    int buf = 0;
    for (int k0 = BKT; k0 <= Kdim; k0 += BKT) {
        const bool more = (k0 < Kdim);
        if (more) {
            #pragma unroll
            for (int r = 0; r < 2; r++)
                aR[r] = *(const float4*)(Ag + (size_t)(bm + am + r * 64) * Kdim + k0 + ak);
            #pragma unroll
            for (int r = 0; r < 2; r++)
                bR[r] = *(const float4*)(Bg + (size_t)(k0 + bk) * Ndim + bn + bn0 + r * 64);
        }

        // ---- compute on buf ----
        {
            const float (*Asb)[SAS] = As[buf];
            const float (*Bsb)[SBS] = Bs[buf];
            #pragma unroll
            for (int kk = 0; kk < BKT; kk += 8) {
                uint32_t af[4][4], bf[4][2];
                #pragma unroll
                for (int mt = 0; mt < 4; mt++) {
                    const int m0 = wm + mt * 16 + g;
                    af[mt][0] = __float_as_uint(Asb[kk + t][m0]);
                    af[mt][1] = __float_as_uint(Asb[kk + t][m0 + 8]);
                    af[mt][2] = __float_as_uint(Asb[kk + t + 4][m0]);
                    af[mt][3] = __float_as_uint(Asb[kk + t + 4][m0 + 8]);
                }
                #pragma unroll
                for (int nt = 0; nt < 4; nt++) {
                    const int n0 = wn + nt * 8 + g;
                    bf[nt][0] = __float_as_uint(Bsb[kk + t][n0]);
                    bf[nt][1] = __float_as_uint(Bsb[kk + t + 4][n0]);
                }
                #pragma unroll
                for (int mt = 0; mt < 4; mt++)
                    #pragma unroll
                    for (int nt = 0; nt < 4; nt++)
                        mma_tf32(acc[mt][nt], af[mt], bf[nt]);
            }
        }

        if (more) {
            const int nb = buf ^ 1;
            #pragma unroll
            for (int r = 0; r < 2; r++) {
                As[nb][ak + 0][am + r * 64] = to_tf32(aR[r].x);
                As[nb][ak + 1][am + r * 64] = to_tf32(aR[r].y);
                As[nb][ak + 2][am + r * 64] = to_tf32(aR[r].z);
                As[nb][ak + 3][am + r * 64] = to_tf32(aR[r].w);
            }
            #pragma unroll
            for (int r = 0; r < 2; r++) {
                float4 v;
                v.x = to_tf32(bR[r].x); v.y = to_tf32(bR[r].y);
                v.z = to_tf32(bR[r].z); v.w = to_tf32(bR[r].w);
                *(float4*)&Bs[nb][bk][bn0 + r * 64] = v;
            }
            __syncthreads();
            buf = nb;
        }
    }

    // ---- epilogue ----
    if (PHASE == 1) {
        // gelu -> Cout (= g_H), row stride Ndim
        #pragma unroll
        for (int mt = 0; mt < 4; mt++) {
            const int row = bm + wm + mt * 16 + g;
            #pragma unroll
            for (int nt = 0; nt < 4; nt++) {
                const int col = bn + wn + nt * 8 + 2 * t;
                float2 v0, v1;
                v0.x = geluf(acc[mt][nt][0]); v0.y = geluf(acc[mt][nt][1]);
                v1.x = geluf(acc[mt][nt][2]); v1.y = geluf(acc[mt][nt][3]);
                *(float2*)(Cout + (size_t)row * Ndim + col) = v0;
                *(float2*)(Cout + (size_t)(row + 8) * Ndim + col) = v1;
            }
        }
    } else {
        // out[r, n*2048 + c] += wout[r*4+n] * y[r, c]
        #pragma unroll
        for (int mt = 0; mt < 4; mt++) {
            const int row0 = bm + wm + mt * 16 + g;
            const int row1 = row0 + 8;
            float w0[4], w1[4];
            #pragma unroll
            for (int n = 0; n < 4; n++) {
                w0[n] = g_wout[row0 * 4 + n];
                w1[n] = g_wout[row1 * 4 + n];
            }
            #pragma unroll
            for (int nt = 0; nt < 4; nt++) {
                const int col = bn + wn + nt * 8 + 2 * t;
                #pragma unroll
                for (int n = 0; n < 4; n++) {
                    float2* p0 = (float2*)(Cout + (size_t)row0 * IN_DIM + n * BLK + col);
                    float2 o0 = *p0;
                    o0.x = fmaf(w0[n], acc[mt][nt][0], o0.x);
                    o0.y = fmaf(w0[n], acc[mt][nt][1], o0.y);
                    *p0 = o0;
                    float2* p1 = (float2*)(Cout + (size_t)row1 * IN_DIM + n * BLK + col);
                    float2 o1 = *p1;
                    o1.x = fmaf(w1[n], acc[mt][nt][2], o1.x);
                    o1.y = fmaf(w1[n], acc[mt][nt][3], o1.y);
                    *p1 = o1;
                }
            }
        }
    }
}

// ---------------------------------------------------------------------------
extern "C" void kernel_launch(void* const* d_in, const int* in_sizes, int n_in,
                              void* d_out, int out_size)
{
    const float* x      = (const float*)d_in[0];
    const float* p_ri   = (const float*)d_in[1];
    const float* p_wo   = (const float*)d_in[2];
    const float* a_ri   = (const float*)d_in[3];
    const float* a_wo   = (const float*)d_in[4];
    const float* W_ri   = (const float*)d_in[5];
    const float* W_wo   = (const float*)d_in[6];
    const float* ldt_c  = (const float*)d_in[7];
    const float* ldt_d  = (const float*)d_in[8];
    const float* W_dtc  = (const float*)d_in[9];
    const float* b_dtc  = (const float*)d_in[10];
    const float* W_dtd  = (const float*)d_in[11];
    const float* b_dtd  = (const float*)d_in[12];
    const float* cA     = (const float*)d_in[13];
    const float* W_conv = (const float*)d_in[14];
    const float* ddiag  = (const float*)d_in[15];
    const float* W_diss = (const float*)d_in[16];
    const float* W1     = (const float*)d_in[17];
    const float* W2     = (const float*)d_in[18];
    float* out = (float*)d_out;

    kernelA<<<BSZ, 256>>>(x, p_ri, p_wo, a_ri, a_wo, W_ri, W_wo,
                          ldt_c, ldt_d, W_dtc, b_dtc, W_dtd, b_dtd,
                          cA, W_conv, ddiag, W_diss, out);

    // g_H is written by phase-1 kernel (pass as Cout); phase-2 writes d_out.
    float* gH_dummy = nullptr;  // Cout for phase 1 is the device-global g_H,
                                // referenced inside the kernel? No: pass via symbol-free path.
    (void)gH_dummy;

    dim3 g1(DFF / BN, BSZ / BM);    // (64, 32)
    dim3 g2(EMBED / BN, BSZ / BM);  // (16, 32)

    // Phase 1 writes into g_H: obtain its address via a device-symbol lookup-free
    // trick is not needed — cudaGetSymbolAddress is a host API and allowed.
    static float* gH_ptr = nullptr;
    if (!gH_ptr) cudaGetSymbolAddress((void**)&gH_ptr, g_H);

    mma_gemm<EMBED, DFF, 1><<<g1, 256>>>(W1, gH_ptr);
    mma_gemm<DFF, EMBED, 2><<<g2, 256>>>(W2, out);
}

// round 4
// speedup vs baseline: 3.2016x; 1.2274x over previous
#include <cuda_runtime.h>
#include <math.h>
#include <stdint.h>

// Problem constants
#define BSZ    4096
#define NST    4
#define EMBED  2048
#define DFF    8192
#define IN_DIM 8192   // N*BLOCK = 4*2048
#define BLK    2048

// Scratch (device globals; no allocations allowed)
__device__ float g_branch[(size_t)BSZ * EMBED];   // 32 MB (tf32-rounded)
__device__ float g_H[(size_t)BSZ * DFF];          // 128 MB (tf32-rounded)
__device__ float g_wout[BSZ * NST];
__device__ float g_W1c[(size_t)EMBED * DFF];      // rna(W1) [2048, 8192]
__device__ float g_W2c[(size_t)DFF * EMBED];      // rna(W2) [8192, 2048]

// ---------------------------------------------------------------------------
// Math helpers
// ---------------------------------------------------------------------------
__device__ __forceinline__ float sigf(float v) { return 1.0f / (1.0f + expf(-v)); }
__device__ __forceinline__ float softplusf(float v) {
    return (v > 15.0f) ? v : log1pf(expf(v));
}
__device__ __forceinline__ float geluf(float v) {
    const float c = 0.7978845608028654f;
    float t = tanhf(c * (v + 0.044715f * v * v * v));
    return 0.5f * v * (1.0f + t);
}
__device__ __forceinline__ float to_tf32(float x) {
    uint32_t u;
    asm("cvt.rna.tf32.f32 %0, %1;" : "=r"(u) : "f"(x));
    return __uint_as_float(u);
}
__device__ __forceinline__ void mma_tf32(float* c, const uint32_t* a, const uint32_t* b) {
    asm volatile("mma.sync.aligned.m16n8k8.row.col.f32.tf32.tf32.f32 "
                 "{%0,%1,%2,%3}, {%4,%5,%6,%7}, {%8,%9}, {%0,%1,%2,%3};"
                 : "+f"(c[0]), "+f"(c[1]), "+f"(c[2]), "+f"(c[3])
                 : "r"(a[0]), "r"(a[1]), "r"(a[2]), "r"(a[3]),
                   "r"(b[0]), "r"(b[1]));
}
__device__ __forceinline__ void cp16(uint32_t s, const void* g) {
    asm volatile("cp.async.cg.shared.global [%0], [%1], 16;" :: "r"(s), "l"(g));
}
__device__ __forceinline__ void cp_commit() {
    asm volatile("cp.async.commit_group;" ::: "memory");
}
template<int N>
__device__ __forceinline__ void cp_wait() {
    asm volatile("cp.async.wait_group %0;" :: "n"(N) : "memory");
}
__device__ __forceinline__ uint32_t smem_u32(const void* p) {
    uint32_t a;
    asm("{ .reg .u64 t; cvta.to.shared.u64 t, %1; cvt.u32.u64 %0, t; }" : "=r"(a) : "l"(p));
    return a;
}

// ---------------------------------------------------------------------------
// rna copy of weights (so cp.async path needs no conversion; HW tf32
// truncation in the mma is then exact)
// ---------------------------------------------------------------------------
__global__ void __launch_bounds__(256) rna_copy4(const float4* __restrict__ src,
                                                 float4* __restrict__ dst, int n4)
{
    int i = blockIdx.x * blockDim.x + threadIdx.x;
    if (i < n4) {
        float4 v = src[i];
        v.x = to_tf32(v.x); v.y = to_tf32(v.y);
        v.z = to_tf32(v.z); v.w = to_tf32(v.w);
        dst[i] = v;
    }
}

// ---------------------------------------------------------------------------
// Kernel A: 2 rows per CTA (halves L2 weight re-read traffic).
// grid = 2048, 256 threads, 64KB dynamic smem (2 rows of x).
// ---------------------------------------------------------------------------
__global__ void __launch_bounds__(256) kernelA(
    const float* __restrict__ x,
    const float* __restrict__ p_ri,   const float* __restrict__ p_wo,
    const float* __restrict__ a_ri,   const float* __restrict__ a_wo,
    const float* __restrict__ W_ri,   const float* __restrict__ W_wo,
    const float* __restrict__ ldt_c,  const float* __restrict__ ldt_d,
    const float* __restrict__ W_dtc,  const float* __restrict__ b_dtc,
    const float* __restrict__ W_dtd,  const float* __restrict__ b_dtd,
    const float* __restrict__ cA,     const float* __restrict__ W_conv,
    const float* __restrict__ ddiag,  const float* __restrict__ W_diss,
    float* __restrict__ out)
{
    extern __shared__ float sx[];          // [2 * IN_DIM]
    __shared__ float spart[62 * 8];
    __shared__ float sdots[62];
    __shared__ float sPhi[2][16];
    __shared__ float srin[2][4];

    const int row0 = blockIdx.x * 2;
    const int tid = threadIdx.x;

    // Load 2 contiguous rows (64KB) via float4
    {
        const float4* xr = (const float4*)(x + (size_t)row0 * IN_DIM);
        float4* sx4 = (float4*)sx;
        #pragma unroll 4
        for (int i = tid; i < 2 * IN_DIM / 4; i += 256) sx4[i] = xr[i];
    }
    __syncthreads();

    // 62 accumulators: slot 2j (row0), 2j+1 (row1); j: 0-3 W_ri, 4-7 W_wo,
    // 8-23 W_conv, 24-27 W_diss, 28 W_dtc, 29 W_dtd, 30 sumsq
    float a[62];
    #pragma unroll
    for (int j = 0; j < 62; j++) a[j] = 0.0f;

    for (int k = tid; k < IN_DIM; k += 256) {
        const float x0 = sx[k], x1 = sx[IN_DIM + k];
        a[60] = fmaf(x0, x0, a[60]);
        a[61] = fmaf(x1, x1, a[61]);
        #pragma unroll
        for (int j = 0; j < 4; j++) {
            float w = W_ri[j * IN_DIM + k];
            a[2 * j]     = fmaf(w, x0, a[2 * j]);
            a[2 * j + 1] = fmaf(w, x1, a[2 * j + 1]);
        }
        #pragma unroll
        for (int j = 0; j < 4; j++) {
            float w = W_wo[j * IN_DIM + k];
            a[8 + 2 * j]     = fmaf(w, x0, a[8 + 2 * j]);
            a[8 + 2 * j + 1] = fmaf(w, x1, a[8 + 2 * j + 1]);
        }
        #pragma unroll
        for (int j = 0; j < 16; j++) {
            float w = W_conv[j * IN_DIM + k];
            a[16 + 2 * j]     = fmaf(w, x0, a[16 + 2 * j]);
            a[16 + 2 * j + 1] = fmaf(w, x1, a[16 + 2 * j + 1]);
        }
        #pragma unroll
        for (int j = 0; j < 4; j++) {
            float w = W_diss[j * IN_DIM + k];
            a[48 + 2 * j]     = fmaf(w, x0, a[48 + 2 * j]);
            a[48 + 2 * j + 1] = fmaf(w, x1, a[48 + 2 * j + 1]);
        }
        {
            float w = W_dtc[k];
            a[56] = fmaf(w, x0, a[56]);
            a[57] = fmaf(w, x1, a[57]);
            w = W_dtd[k];
            a[58] = fmaf(w, x0, a[58]);
            a[59] = fmaf(w, x1, a[59]);
        }
    }

    const int lane = tid & 31, wid = tid >> 5;
    #pragma unroll
    for (int j = 0; j < 62; j++) {
        float v = a[j];
        #pragma unroll
        for (int o = 16; o > 0; o >>= 1) v += __shfl_down_sync(0xffffffffu, v, o);
        if (lane == 0) spart[j * 8 + wid] = v;
    }
    __syncthreads();
    if (tid < 62) {
        float s = 0.0f;
        #pragma unroll
        for (int w = 0; w < 8; w++) s += spart[tid * 8 + w];
        sdots[tid] = s;
    }
    __syncthreads();

    if (tid < 2) {
        const int r = tid;       // row within pair
        const int row = row0 + r;
        // slot order within sdots: indices 0..59 interleaved by row; sumsq at 60+r
        const float rstd = rsqrtf(sdots[60 + r] * (1.0f / (float)IN_DIM) + 1.1920929e-7f);
        float h[30];
        #pragma unroll
        for (int j = 0; j < 30; j++) {
            // mapping back: j 0-3 -> sdots[2j+r]; 4-7 -> sdots[8+2(j-4)+r];
            // 8-23 -> sdots[16+2(j-8)+r]; 24-27 -> sdots[48+2(j-24)+r];
            // 28 -> sdots[56+r]; 29 -> sdots[58+r]
            int base;
            if (j < 4)       base = 2 * j;
            else if (j < 8)  base = 8 + 2 * (j - 4);
            else if (j < 24) base = 16 + 2 * (j - 8);
            else if (j < 28) base = 48 + 2 * (j - 24);
            else if (j == 28) base = 56;
            else             base = 58;
            h[j] = sdots[base + r] * rstd;
        }

        const float ari = a_ri[0], awo = a_wo[0];
        #pragma unroll
        for (int n = 0; n < 4; n++) {
            srin[r][n] = sigf(ari * h[n] + p_ri[n]);
            g_wout[row * 4 + n] = 2.0f * sigf(awo * h[4 + n] + p_wo[n]);
        }

        const float dtc = 1e-3f + 0.999f * sigf(ldt_c[0] + h[28] + b_dtc[0]);
        const float dtd = 1e-3f + 0.999f * sigf(ldt_d[0] + h[29] + b_dtd[0]);

        float Mm[4][4];
        #pragma unroll
        for (int i = 0; i < 4; i++)
            #pragma unroll
            for (int j = 0; j < 4; j++)
                Mm[i][j] = cA[i * 4 + j] + h[8 + i * 4 + j];

        float S[4][4];
        #pragma unroll
        for (int i = 0; i < 4; i++)
            #pragma unroll
            for (int j = 0; j < 4; j++)
                S[i][j] = 0.5f * (Mm[i][j] - Mm[j][i]) * dtc;

        float ehD[4];
        #pragma unroll
        for (int n = 0; n < 4; n++) {
            float dd = softplusf(ddiag[n] + h[24 + n]);
            ehD[n] = expf(-0.5f * dtd * dd);
        }

        float A[4][4], X[4][4];
        #pragma unroll
        for (int i = 0; i < 4; i++)
            #pragma unroll
            for (int j = 0; j < 4; j++) {
                float id = (i == j) ? 1.0f : 0.0f;
                A[i][j] = id - S[i][j];
                X[i][j] = id + S[i][j];
            }
        #pragma unroll
        for (int p = 0; p < 4; p++) {
            float inv = 1.0f / A[p][p];
            #pragma unroll
            for (int j = 0; j < 4; j++) { A[p][j] *= inv; X[p][j] *= inv; }
            #pragma unroll
            for (int rr = 0; rr < 4; rr++) {
                if (rr == p) continue;
                float f = A[rr][p];
                #pragma unroll
                for (int j = 0; j < 4; j++) {
                    A[rr][j] = fmaf(-f, A[p][j], A[rr][j]);
                    X[rr][j] = fmaf(-f, X[p][j], X[rr][j]);
                }
            }
        }
        #pragma unroll
        for (int i = 0; i < 4; i++)
            #pragma unroll
            for (int j = 0; j < 4; j++)
                sPhi[r][i * 4 + j] = ehD[i] * X[i][j] * ehD[j];
    }
    __syncthreads();

    #pragma unroll
    for (int r = 0; r < 2; r++) {
        const int row = row0 + r;
        const float* sxr = sx + r * IN_DIM;
        const float r0 = srin[r][0], r1 = srin[r][1], r2 = srin[r][2], r3 = srin[r][3];
        float ph[16];
        #pragma unroll
        for (int i = 0; i < 16; i++) ph[i] = sPhi[r][i];

        for (int c = tid; c < BLK; c += 256) {
            float x0 = sxr[c], x1 = sxr[BLK + c], x2 = sxr[2 * BLK + c], x3 = sxr[3 * BLK + c];
            g_branch[(size_t)row * BLK + c] = to_tf32(r0 * x0 + r1 * x1 + r2 * x2 + r3 * x3);
            #pragma unroll
            for (int i = 0; i < 4; i++) {
                out[(size_t)row * IN_DIM + i * BLK + c] =
                    ph[i * 4 + 0] * x0 + ph[i * 4 + 1] * x1 + ph[i * 4 + 2] * x2 + ph[i * 4 + 3] * x3;
            }
        }
    }
}

// ---------------------------------------------------------------------------
// TF32 mma.sync GEMM: CTA 128x256, BK=32, 512 threads (16 warps, warp 32x64),
// 2-stage cp.async pipeline, conflict-free padded smem.
// PHASE 1: g_H = rna(gelu(g_branch @ W1c))   (Kdim=2048, Ng=8192)
// PHASE 2: out += wout * (g_H @ W2c)         (Kdim=8192, Ng=2048)
// ---------------------------------------------------------------------------
#define GBM 128
#define GBN 256
#define GBK 32
#define ASTR 36                      // floats (pad: bank = 4m+t, conflict-free)
#define BSTR 264                     // floats (pad: bank = 8k+n, conflict-free)
#define A_STAGE_B (GBM * ASTR * 4)   // 18432 B
#define B_STAGE_B (GBK * BSTR * 4)   // 33792 B
#define STAGE_B   (A_STAGE_B + B_STAGE_B)   // 52224 B
#define GEMM_SMEM (2 * STAGE_B)             // 104448 B

template<int Kdim, int Ndim, int PHASE>
__global__ void __launch_bounds__(512) tc_gemm(
    const float* __restrict__ Ag,
    const float* __restrict__ Bg,
    float* __restrict__ Cout)
{
    extern __shared__ char smem[];
    const uint32_t sb = smem_u32(smem);

    const int tid  = threadIdx.x;
    const int wid  = tid >> 5;
    const int lane = tid & 31;
    const int g = lane >> 2, t = lane & 3;
    const int wm = (wid & 3) * 32;       // 4 warps along M
    const int wn = (wid >> 2) * 64;      // 4 warps along N
    const int bm = blockIdx.y * GBM;
    const int bn = blockIdx.x * GBN;

    // load mapping: A 1024 16B-chunks (2/thread), B 2048 chunks (4/thread)
    const int aRow0 = tid >> 3;          // id = tid: row 0..63
    const int aKc   = tid & 7;
    const int bNc   = tid & 63;

    // accumulators: warp tile 32x64 -> mt=2 (m16), nt=8 (n8)
    float acc[2][8][4];
    #pragma unroll
    for (int i = 0; i < 2; i++)
        #pragma unroll
        for (int j = 0; j < 8; j++)
            #pragma unroll
            for (int q = 0; q < 4; q++) acc[i][j][q] = 0.0f;

    auto load_stage = [&](int stage, int buf) {
        const uint32_t Ab = sb + buf * STAGE_B;
        const uint32_t Bb = Ab + A_STAGE_B;
        const int k0 = stage * GBK;
        // A: rows of Ag (m-major, K contiguous)
        #pragma unroll
        for (int j = 0; j < 2; j++) {
            const int row = aRow0 + j * 64;
            cp16(Ab + (uint32_t)(row * (ASTR * 4) + aKc * 16),
                 Ag + (size_t)(bm + row) * Kdim + k0 + aKc * 4);
        }
        // B: rows of Bg (k-major, N contiguous)
        #pragma unroll
        for (int j = 0; j < 4; j++) {
            const int id = tid + j * 512;
            const int row = id >> 6;
            cp16(Bb + (uint32_t)(row * (BSTR * 4) + bNc * 16),
                 Bg + (size_t)(k0 + row) * Ndim + bn + bNc * 4);
        }
    };

    const int NCH = Kdim / GBK;

    load_stage(0, 0); cp_commit();
    load_stage(1, 1); cp_commit();

    for (int i = 0; i < NCH; i++) {
        cp_wait<1>();
        __syncthreads();

        const int buf = i & 1;
        const char* Abase = smem + buf * STAGE_B;
        const char* Bbase = Abase + A_STAGE_B;

        #pragma unroll
        for (int kk = 0; kk < GBK; kk += 8) {
            uint32_t af[2][4], bf[8][2];
            #pragma unroll
            for (int mt = 0; mt < 2; mt++) {
                const int m0 = wm + mt * 16 + g;
                const uint32_t* r0 = (const uint32_t*)(Abase + (size_t)m0 * (ASTR * 4));
                const uint32_t* r1 = (const uint32_t*)(Abase + (size_t)(m0 + 8) * (ASTR * 4));
                af[mt][0] = r0[kk + t];
                af[mt][1] = r1[kk + t];
                af[mt][2] = r0[kk + t + 4];
                af[mt][3] = r1[kk + t + 4];
            }
            #pragma unroll
            for (int nt = 0; nt < 8; nt++) {
                const int n0 = wn + nt * 8 + g;
                bf[nt][0] = *(const uint32_t*)(Bbase + (size_t)(kk + t) * (BSTR * 4) + n0 * 4);
                bf[nt][1] = *(const uint32_t*)(Bbase + (size_t)(kk + t + 4) * (BSTR * 4) + n0 * 4);
            }
            #pragma unroll
            for (int mt = 0; mt < 2; mt++)
                #pragma unroll
                for (int nt = 0; nt < 8; nt++)
                    mma_tf32(acc[mt][nt], af[mt], bf[nt]);
        }
        __syncthreads();

        if (i + 2 < NCH) load_stage(i + 2, buf);
        cp_commit();   // always commit (possibly empty) to keep group count aligned
    }

    // epilogue
    #pragma unroll
    for (int mt = 0; mt < 2; mt++) {
        const int row0 = bm + wm + mt * 16 + g;
        const int row1 = row0 + 8;
        if (PHASE == 1) {
            #pragma unroll
            for (int nt = 0; nt < 8; nt++) {
                const int col = bn + wn + nt * 8 + 2 * t;
                float2 v0, v1;
                v0.x = to_tf32(geluf(acc[mt][nt][0]));
                v0.y = to_tf32(geluf(acc[mt][nt][1]));
                v1.x = to_tf32(geluf(acc[mt][nt][2]));
                v1.y = to_tf32(geluf(acc[mt][nt][3]));
                *(float2*)(Cout + (size_t)row0 * Ndim + col) = v0;
                *(float2*)(Cout + (size_t)row1 * Ndim + col) = v1;
            }
        } else {
            float w0[4], w1[4];
            #pragma unroll
            for (int n = 0; n < 4; n++) {
                w0[n] = g_wout[row0 * 4 + n];
                w1[n] = g_wout[row1 * 4 + n];
            }
            #pragma unroll
            for (int nt = 0; nt < 8; nt++) {
                const int col = bn + wn + nt * 8 + 2 * t;
                #pragma unroll
                for (int n = 0; n < 4; n++) {
                    float2* p0 = (float2*)(Cout + (size_t)row0 * IN_DIM + n * BLK + col);
                    float2 o0 = *p0;
                    o0.x = fmaf(w0[n], acc[mt][nt][0], o0.x);
                    o0.y = fmaf(w0[n], acc[mt][nt][1], o0.y);
                    *p0 = o0;
                    float2* p1 = (float2*)(Cout + (size_t)row1 * IN_DIM + n * BLK + col);
                    float2 o1 = *p1;
                    o1.x = fmaf(w1[n], acc[mt][nt][2], o1.x);
                    o1.y = fmaf(w1[n], acc[mt][nt][3], o1.y);
                    *p1 = o1;
                }
            }
        }
    }
}

// ---------------------------------------------------------------------------
extern "C" void kernel_launch(void* const* d_in, const int* in_sizes, int n_in,
                              void* d_out, int out_size)
{
    const float* x      = (const float*)d_in[0];
    const float* p_ri   = (const float*)d_in[1];
    const float* p_wo   = (const float*)d_in[2];
    const float* a_ri   = (const float*)d_in[3];
    const float* a_wo   = (const float*)d_in[4];
    const float* W_ri   = (const float*)d_in[5];
    const float* W_wo   = (const float*)d_in[6];
    const float* ldt_c  = (const float*)d_in[7];
    const float* ldt_d  = (const float*)d_in[8];
    const float* W_dtc  = (const float*)d_in[9];
    const float* b_dtc  = (const float*)d_in[10];
    const float* W_dtd  = (const float*)d_in[11];
    const float* b_dtd  = (const float*)d_in[12];
    const float* cA     = (const float*)d_in[13];
    const float* W_conv = (const float*)d_in[14];
    const float* ddiag  = (const float*)d_in[15];
    const float* W_diss = (const float*)d_in[16];
    const float* W1     = (const float*)d_in[17];
    const float* W2     = (const float*)d_in[18];
    float* out = (float*)d_out;

    float *gH, *gBr, *gW1c, *gW2c;
    cudaGetSymbolAddress((void**)&gH,   g_H);
    cudaGetSymbolAddress((void**)&gBr,  g_branch);
    cudaGetSymbolAddress((void**)&gW1c, g_W1c);
    cudaGetSymbolAddress((void**)&gW2c, g_W2c);

    cudaFuncSetAttribute(kernelA, cudaFuncAttributeMaxDynamicSharedMemorySize, 2 * IN_DIM * 4);
    cudaFuncSetAttribute(tc_gemm<EMBED, DFF, 1>, cudaFuncAttributeMaxDynamicSharedMemorySize, GEMM_SMEM);
    cudaFuncSetAttribute(tc_gemm<DFF, EMBED, 2>, cudaFuncAttributeMaxDynamicSharedMemorySize, GEMM_SMEM);

    // rna weight copies
    const int n4 = (EMBED * DFF) / 4;
    rna_copy4<<<(n4 + 255) / 256, 256>>>((const float4*)W1, (float4*)gW1c, n4);
    rna_copy4<<<(n4 + 255) / 256, 256>>>((const float4*)W2, (float4*)gW2c, n4);

    kernelA<<<BSZ / 2, 256, 2 * IN_DIM * 4>>>(
        x, p_ri, p_wo, a_ri, a_wo, W_ri, W_wo,
        ldt_c, ldt_d, W_dtc, b_dtc, W_dtd, b_dtd,
        cA, W_conv, ddiag, W_diss, out);

    tc_gemm<EMBED, DFF, 1><<<dim3(DFF / GBN, BSZ / GBM), 512, GEMM_SMEM>>>(gBr, gW1c, gH);
    tc_gemm<DFF, EMBED, 2><<<dim3(EMBED / GBN, BSZ / GBM), 512, GEMM_SMEM>>>(gH, gW2c, out);
}

// round 6
// speedup vs baseline: 3.2035x; 1.0006x over previous
#include <cuda_runtime.h>
#include <math.h>
#include <stdint.h>

// Problem constants
#define BSZ    4096
#define NST    4
#define EMBED  2048
#define DFF    8192
#define IN_DIM 8192   // N*BLOCK = 4*2048
#define BLK    2048

// Scratch (device globals; no allocations allowed)
__device__ float g_branch[(size_t)BSZ * EMBED];   // 32 MB (tf32-rounded)
__device__ float g_H[(size_t)BSZ * DFF];          // 128 MB (tf32-rounded)
__device__ float g_wout[BSZ * NST];
__device__ float g_W1c[(size_t)EMBED * DFF];      // rna(W1) [2048, 8192]
__device__ float g_W2c[(size_t)DFF * EMBED];      // rna(W2) [8192, 2048]

// ---------------------------------------------------------------------------
// Math helpers
// ---------------------------------------------------------------------------
__device__ __forceinline__ float sigf(float v) { return 1.0f / (1.0f + expf(-v)); }
__device__ __forceinline__ float softplusf(float v) {
    return (v > 15.0f) ? v : log1pf(expf(v));
}
__device__ __forceinline__ float geluf(float v) {
    const float c = 0.7978845608028654f;
    float t = tanhf(c * (v + 0.044715f * v * v * v));
    return 0.5f * v * (1.0f + t);
}
__device__ __forceinline__ float to_tf32(float x) {
    uint32_t u;
    asm("cvt.rna.tf32.f32 %0, %1;" : "=r"(u) : "f"(x));
    return __uint_as_float(u);
}
__device__ __forceinline__ void mma_tf32(float* c, const uint32_t* a, const uint32_t* b) {
    asm volatile("mma.sync.aligned.m16n8k8.row.col.f32.tf32.tf32.f32 "
                 "{%0,%1,%2,%3}, {%4,%5,%6,%7}, {%8,%9}, {%0,%1,%2,%3};"
                 : "+f"(c[0]), "+f"(c[1]), "+f"(c[2]), "+f"(c[3])
                 : "r"(a[0]), "r"(a[1]), "r"(a[2]), "r"(a[3]),
                   "r"(b[0]), "r"(b[1]));
}
__device__ __forceinline__ void cp16(uint32_t s, const void* g) {
    asm volatile("cp.async.cg.shared.global [%0], [%1], 16;" :: "r"(s), "l"(g));
}
__device__ __forceinline__ void cp_commit() {
    asm volatile("cp.async.commit_group;" ::: "memory");
}
template<int N>
__device__ __forceinline__ void cp_wait() {
    asm volatile("cp.async.wait_group %0;" :: "n"(N) : "memory");
}
__device__ __forceinline__ uint32_t smem_u32(const void* p) {
    uint32_t a;
    asm("{ .reg .u64 t; cvta.to.shared.u64 t, %1; cvt.u32.u64 %0, t; }" : "=r"(a) : "l"(p));
    return a;
}

// ---------------------------------------------------------------------------
// rna copy of weights
// ---------------------------------------------------------------------------
__global__ void __launch_bounds__(256) rna_copy4(const float4* __restrict__ src,
                                                 float4* __restrict__ dst, int n4)
{
    int i = blockIdx.x * blockDim.x + threadIdx.x;
    if (i < n4) {
        float4 v = src[i];
        v.x = to_tf32(v.x); v.y = to_tf32(v.y);
        v.z = to_tf32(v.z); v.w = to_tf32(v.w);
        dst[i] = v;
    }
}

// ---------------------------------------------------------------------------
// Kernel A: 2 rows per CTA (halves L2 weight re-read traffic).
// grid = 2048, 256 threads, 64KB dynamic smem (2 rows of x).
// ---------------------------------------------------------------------------
__global__ void __launch_bounds__(256) kernelA(
    const float* __restrict__ x,
    const float* __restrict__ p_ri,   const float* __restrict__ p_wo,
    const float* __restrict__ a_ri,   const float* __restrict__ a_wo,
    const float* __restrict__ W_ri,   const float* __restrict__ W_wo,
    const float* __restrict__ ldt_c,  const float* __restrict__ ldt_d,
    const float* __restrict__ W_dtc,  const float* __restrict__ b_dtc,
    const float* __restrict__ W_dtd,  const float* __restrict__ b_dtd,
    const float* __restrict__ cA,     const float* __restrict__ W_conv,
    const float* __restrict__ ddiag,  const float* __restrict__ W_diss,
    float* __restrict__ out)
{
    extern __shared__ float sx[];          // [2 * IN_DIM]
    __shared__ float spart[62 * 8];
    __shared__ float sdots[62];
    __shared__ float sPhi[2][16];
    __shared__ float srin[2][4];

    const int row0 = blockIdx.x * 2;
    const int tid = threadIdx.x;

    {
        const float4* xr = (const float4*)(x + (size_t)row0 * IN_DIM);
        float4* sx4 = (float4*)sx;
        #pragma unroll 4
        for (int i = tid; i < 2 * IN_DIM / 4; i += 256) sx4[i] = xr[i];
    }
    __syncthreads();

    float a[62];
    #pragma unroll
    for (int j = 0; j < 62; j++) a[j] = 0.0f;

    for (int k = tid; k < IN_DIM; k += 256) {
        const float x0 = sx[k], x1 = sx[IN_DIM + k];
        a[60] = fmaf(x0, x0, a[60]);
        a[61] = fmaf(x1, x1, a[61]);
        #pragma unroll
        for (int j = 0; j < 4; j++) {
            float w = W_ri[j * IN_DIM + k];
            a[2 * j]     = fmaf(w, x0, a[2 * j]);
            a[2 * j + 1] = fmaf(w, x1, a[2 * j + 1]);
        }
        #pragma unroll
        for (int j = 0; j < 4; j++) {
            float w = W_wo[j * IN_DIM + k];
            a[8 + 2 * j]     = fmaf(w, x0, a[8 + 2 * j]);
            a[8 + 2 * j + 1] = fmaf(w, x1, a[8 + 2 * j + 1]);
        }
        #pragma unroll
        for (int j = 0; j < 16; j++) {
            float w = W_conv[j * IN_DIM + k];
            a[16 + 2 * j]     = fmaf(w, x0, a[16 + 2 * j]);
            a[16 + 2 * j + 1] = fmaf(w, x1, a[16 + 2 * j + 1]);
        }
        #pragma unroll
        for (int j = 0; j < 4; j++) {
            float w = W_diss[j * IN_DIM + k];
            a[48 + 2 * j]     = fmaf(w, x0, a[48 + 2 * j]);
            a[48 + 2 * j + 1] = fmaf(w, x1, a[48 + 2 * j + 1]);
        }
        {
            float w = W_dtc[k];
            a[56] = fmaf(w, x0, a[56]);
            a[57] = fmaf(w, x1, a[57]);
            w = W_dtd[k];
            a[58] = fmaf(w, x0, a[58]);
            a[59] = fmaf(w, x1, a[59]);
        }
    }

    const int lane = tid & 31, wid = tid >> 5;
    #pragma unroll
    for (int j = 0; j < 62; j++) {
        float v = a[j];
        #pragma unroll
        for (int o = 16; o > 0; o >>= 1) v += __shfl_down_sync(0xffffffffu, v, o);
        if (lane == 0) spart[j * 8 + wid] = v;
    }
    __syncthreads();
    if (tid < 62) {
        float s = 0.0f;
        #pragma unroll
        for (int w = 0; w < 8; w++) s += spart[tid * 8 + w];
        sdots[tid] = s;
    }
    __syncthreads();

    if (tid < 2) {
        const int r = tid;
        const int row = row0 + r;
        const float rstd = rsqrtf(sdots[60 + r] * (1.0f / (float)IN_DIM) + 1.1920929e-7f);
        float h[30];
        #pragma unroll
        for (int j = 0; j < 30; j++) {
            int base;
            if (j < 4)       base = 2 * j;
            else if (j < 8)  base = 8 + 2 * (j - 4);
            else if (j < 24) base = 16 + 2 * (j - 8);
            else if (j < 28) base = 48 + 2 * (j - 24);
            else if (j == 28) base = 56;
            else             base = 58;
            h[j] = sdots[base + r] * rstd;
        }

        const float ari = a_ri[0], awo = a_wo[0];
        #pragma unroll
        for (int n = 0; n < 4; n++) {
            srin[r][n] = sigf(ari * h[n] + p_ri[n]);
            g_wout[row * 4 + n] = 2.0f * sigf(awo * h[4 + n] + p_wo[n]);
        }

        const float dtc = 1e-3f + 0.999f * sigf(ldt_c[0] + h[28] + b_dtc[0]);
        const float dtd = 1e-3f + 0.999f * sigf(ldt_d[0] + h[29] + b_dtd[0]);

        float Mm[4][4];
        #pragma unroll
        for (int i = 0; i < 4; i++)
            #pragma unroll
            for (int j = 0; j < 4; j++)
                Mm[i][j] = cA[i * 4 + j] + h[8 + i * 4 + j];

        float S[4][4];
        #pragma unroll
        for (int i = 0; i < 4; i++)
            #pragma unroll
            for (int j = 0; j < 4; j++)
                S[i][j] = 0.5f * (Mm[i][j] - Mm[j][i]) * dtc;

        float ehD[4];
        #pragma unroll
        for (int n = 0; n < 4; n++) {
            float dd = softplusf(ddiag[n] + h[24 + n]);
            ehD[n] = expf(-0.5f * dtd * dd);
        }

        float A[4][4], X[4][4];
        #pragma unroll
        for (int i = 0; i < 4; i++)
            #pragma unroll
            for (int j = 0; j < 4; j++) {
                float id = (i == j) ? 1.0f : 0.0f;
                A[i][j] = id - S[i][j];
                X[i][j] = id + S[i][j];
            }
        #pragma unroll
        for (int p = 0; p < 4; p++) {
            float inv = 1.0f / A[p][p];
            #pragma unroll
            for (int j = 0; j < 4; j++) { A[p][j] *= inv; X[p][j] *= inv; }
            #pragma unroll
            for (int rr = 0; rr < 4; rr++) {
                if (rr == p) continue;
                float f = A[rr][p];
                #pragma unroll
                for (int j = 0; j < 4; j++) {
                    A[rr][j] = fmaf(-f, A[p][j], A[rr][j]);
                    X[rr][j] = fmaf(-f, X[p][j], X[rr][j]);
                }
            }
        }
        #pragma unroll
        for (int i = 0; i < 4; i++)
            #pragma unroll
            for (int j = 0; j < 4; j++)
                sPhi[r][i * 4 + j] = ehD[i] * X[i][j] * ehD[j];
    }
    __syncthreads();

    #pragma unroll
    for (int r = 0; r < 2; r++) {
        const int row = row0 + r;
        const float* sxr = sx + r * IN_DIM;
        const float r0 = srin[r][0], r1 = srin[r][1], r2 = srin[r][2], r3 = srin[r][3];
        float ph[16];
        #pragma unroll
        for (int i = 0; i < 16; i++) ph[i] = sPhi[r][i];

        for (int c = tid; c < BLK; c += 256) {
            float x0 = sxr[c], x1 = sxr[BLK + c], x2 = sxr[2 * BLK + c], x3 = sxr[3 * BLK + c];
            g_branch[(size_t)row * BLK + c] = to_tf32(r0 * x0 + r1 * x1 + r2 * x2 + r3 * x3);
            #pragma unroll
            for (int i = 0; i < 4; i++) {
                out[(size_t)row * IN_DIM + i * BLK + c] =
                    ph[i * 4 + 0] * x0 + ph[i * 4 + 1] * x1 + ph[i * 4 + 2] * x2 + ph[i * 4 + 3] * x3;
            }
        }
    }
}

// ---------------------------------------------------------------------------
// TF32 mma.sync GEMM: CTA 128x256, BK=32, 256 threads (8 warps, warp 64x64),
// 3-stage cp.async pipeline, conflict-free padded smem.
// LDS:MMA per k-step = 32:32 -> tensor-bound.
// PHASE 1: g_H = rna(gelu(g_branch @ W1c))   (Kdim=2048, Ndim=8192)
// PHASE 2: out += wout * (g_H @ W2c)         (Kdim=8192, Ndim=2048)
// ---------------------------------------------------------------------------
#define GBM 128
#define GBN 256
#define GBK 32
#define ASTR 36                      // floats; bank = 4g+t -> conflict-free
#define BSTR 264                     // floats; bank = 8((t+nt)&3)+g -> conflict-free
#define A_STAGE_B (GBM * ASTR * 4)   // 18432 B
#define B_STAGE_B (GBK * BSTR * 4)   // 33792 B
#define STAGE_B   (A_STAGE_B + B_STAGE_B)   // 52224 B
#define GEMM_SMEM (3 * STAGE_B)             // 156672 B

template<int Kdim, int Ndim, int PHASE>
__global__ void __launch_bounds__(256, 1) tc_gemm(
    const float* __restrict__ Ag,
    const float* __restrict__ Bg,
    float* __restrict__ Cout)
{
    extern __shared__ char smem[];
    const uint32_t sb = smem_u32(smem);

    const int tid  = threadIdx.x;
    const int wid  = tid >> 5;
    const int lane = tid & 31;
    const int g = lane >> 2, t = lane & 3;
    const int wm = (wid & 1) * 64;       // 2 warps along M
    const int wn = (wid >> 1) * 64;      // 4 warps along N
    const int bm = blockIdx.y * GBM;
    const int bn = blockIdx.x * GBN;

    // accumulators: warp tile 64x64 -> mt=4 (m16), nt=8 (n8)
    float acc[4][8][4];
    #pragma unroll
    for (int i = 0; i < 4; i++)
        #pragma unroll
        for (int j = 0; j < 8; j++)
            #pragma unroll
            for (int q = 0; q < 4; q++) acc[i][j][q] = 0.0f;

    auto load_stage = [&](int stage, int buf) {
        const uint32_t Ab = sb + buf * STAGE_B;
        const uint32_t Bb = Ab + A_STAGE_B;
        const int k0 = stage * GBK;
        // A: 128 rows x 8 16B-chunks = 1024 chunks, 4/thread
        #pragma unroll
        for (int j = 0; j < 4; j++) {
            const int c = tid + j * 256;
            const int row = c >> 3, kc = c & 7;
            cp16(Ab + (uint32_t)(row * (ASTR * 4) + kc * 16),
                 Ag + (size_t)(bm + row) * Kdim + k0 + kc * 4);
        }
        // B: 32 rows x 64 16B-chunks = 2048 chunks, 8/thread
        #pragma unroll
        for (int j = 0; j < 8; j++) {
            const int c = tid + j * 256;
            const int row = c >> 6, nc = c & 63;
            cp16(Bb + (uint32_t)(row * (BSTR * 4) + nc * 16),
                 Bg + (size_t)(k0 + row) * Ndim + bn + nc * 4);
        }
    };

    const int NCH = Kdim / GBK;

    load_stage(0, 0); cp_commit();
    load_stage(1, 1); cp_commit();

    for (int i = 0; i < NCH; i++) {
        cp_wait<1>();
        __syncthreads();

        const int buf = i % 3;
        const char* Abase = smem + buf * STAGE_B;
        const char* Bbase = Abase + A_STAGE_B;

        #pragma unroll
        for (int kk = 0; kk < GBK; kk += 8) {
            uint32_t af[4][4], bf[8][2];
            #pragma unroll
            for (int mt = 0; mt < 4; mt++) {
                const int m0 = wm + mt * 16 + g;
                const uint32_t* r0 = (const uint32_t*)(Abase + (size_t)m0 * (ASTR * 4));
                const uint32_t* r1 = (const uint32_t*)(Abase + (size_t)(m0 + 8) * (ASTR * 4));
                af[mt][0] = r0[kk + t];
                af[mt][1] = r1[kk + t];
                af[mt][2] = r0[kk + t + 4];
                af[mt][3] = r1[kk + t + 4];
            }
            #pragma unroll
            for (int nt = 0; nt < 8; nt++) {
                const int n0 = wn + nt * 8 + g;
                bf[nt][0] = *(const uint32_t*)(Bbase + (size_t)(kk + t) * (BSTR * 4) + n0 * 4);
                bf[nt][1] = *(const uint32_t*)(Bbase + (size_t)(kk + t + 4) * (BSTR * 4) + n0 * 4);
            }
            #pragma unroll
            for (int mt = 0; mt < 4; mt++)
                #pragma unroll
                for (int nt = 0; nt < 8; nt++)
                    mma_tf32(acc[mt][nt], af[mt], bf[nt]);
        }
        __syncthreads();

        if (i + 2 < NCH) load_stage(i + 2, (i + 2) % 3);
        cp_commit();   // always commit to keep group accounting aligned
    }

    // epilogue
    #pragma unroll
    for (int mt = 0; mt < 4; mt++) {
        const int row0 = bm + wm + mt * 16 + g;
        const int row1 = row0 + 8;
        if (PHASE == 1) {
            #pragma unroll
            for (int nt = 0; nt < 8; nt++) {
                const int col = bn + wn + nt * 8 + 2 * t;
                float2 v0, v1;
                v0.x = to_tf32(geluf(acc[mt][nt][0]));
                v0.y = to_tf32(geluf(acc[mt][nt][1]));
                v1.x = to_tf32(geluf(acc[mt][nt][2]));
                v1.y = to_tf32(geluf(acc[mt][nt][3]));
                *(float2*)(Cout + (size_t)row0 * Ndim + col) = v0;
                *(float2*)(Cout + (size_t)row1 * Ndim + col) = v1;
            }
        } else {
            float w0[4], w1[4];
            #pragma unroll
            for (int n = 0; n < 4; n++) {
                w0[n] = g_wout[row0 * 4 + n];
                w1[n] = g_wout[row1 * 4 + n];
            }
            #pragma unroll
            for (int nt = 0; nt < 8; nt++) {
                const int col = bn + wn + nt * 8 + 2 * t;
                #pragma unroll
                for (int n = 0; n < 4; n++) {
                    float2* p0 = (float2*)(Cout + (size_t)row0 * IN_DIM + n * BLK + col);
                    float2 o0 = *p0;
                    o0.x = fmaf(w0[n], acc[mt][nt][0], o0.x);
                    o0.y = fmaf(w0[n], acc[mt][nt][1], o0.y);
                    *p0 = o0;
                    float2* p1 = (float2*)(Cout + (size_t)row1 * IN_DIM + n * BLK + col);
                    float2 o1 = *p1;
                    o1.x = fmaf(w1[n], acc[mt][nt][2], o1.x);
                    o1.y = fmaf(w1[n], acc[mt][nt][3], o1.y);
                    *p1 = o1;
                }
            }
        }
    }
}

// ---------------------------------------------------------------------------
extern "C" void kernel_launch(void* const* d_in, const int* in_sizes, int n_in,
                              void* d_out, int out_size)
{
    const float* x      = (const float*)d_in[0];
    const float* p_ri   = (const float*)d_in[1];
    const float* p_wo   = (const float*)d_in[2];
    const float* a_ri   = (const float*)d_in[3];
    const float* a_wo   = (const float*)d_in[4];
    const float* W_ri   = (const float*)d_in[5];
    const float* W_wo   = (const float*)d_in[6];
    const float* ldt_c  = (const float*)d_in[7];
    const float* ldt_d  = (const float*)d_in[8];
    const float* W_dtc  = (const float*)d_in[9];
    const float* b_dtc  = (const float*)d_in[10];
    const float* W_dtd  = (const float*)d_in[11];
    const float* b_dtd  = (const float*)d_in[12];
    const float* cA     = (const float*)d_in[13];
    const float* W_conv = (const float*)d_in[14];
    const float* ddiag  = (const float*)d_in[15];
    const float* W_diss = (const float*)d_in[16];
    const float* W1     = (const float*)d_in[17];
    const float* W2     = (const float*)d_in[18];
    float* out = (float*)d_out;

    float *gH, *gBr, *gW1c, *gW2c;
    cudaGetSymbolAddress((void**)&gH,   g_H);
    cudaGetSymbolAddress((void**)&gBr,  g_branch);
    cudaGetSymbolAddress((void**)&gW1c, g_W1c);
    cudaGetSymbolAddress((void**)&gW2c, g_W2c);

    cudaFuncSetAttribute(kernelA, cudaFuncAttributeMaxDynamicSharedMemorySize, 2 * IN_DIM * 4);
    cudaFuncSetAttribute(tc_gemm<EMBED, DFF, 1>, cudaFuncAttributeMaxDynamicSharedMemorySize, GEMM_SMEM);
    cudaFuncSetAttribute(tc_gemm<DFF, EMBED, 2>, cudaFuncAttributeMaxDynamicSharedMemorySize, GEMM_SMEM);

    const int n4 = (EMBED * DFF) / 4;
    rna_copy4<<<(n4 + 255) / 256, 256>>>((const float4*)W1, (float4*)gW1c, n4);
    rna_copy4<<<(n4 + 255) / 256, 256>>>((const float4*)W2, (float4*)gW2c, n4);

    kernelA<<<BSZ / 2, 256, 2 * IN_DIM * 4>>>(
        x, p_ri, p_wo, a_ri, a_wo, W_ri, W_wo,
        ldt_c, ldt_d, W_dtc, b_dtc, W_dtd, b_dtd,
        cA, W_conv, ddiag, W_diss, out);

    tc_gemm<EMBED, DFF, 1><<<dim3(DFF / GBN, BSZ / GBM), 256, GEMM_SMEM>>>(gBr, gW1c, gH);
    tc_gemm<DFF, EMBED, 2><<<dim3(EMBED / GBN, BSZ / GBM), 256, GEMM_SMEM>>>(gH, gW2c, out);
}